// round 3
// baseline (speedup 1.0000x reference)
#include <cuda_runtime.h>
#include <cuda_bf16.h>

// out[row,m] = ( fp32FWHT_m( sum_d fma-chain x[row,d]*W[m,d] ) * (1/sqrt(128)) > 0 ) ? 1 : 0
//
// Bit-exact vs CPU fp32 reference (verified rel_err == 0.0 in R2):
//  - one fp32 accumulator per output, strictly sequential fma.rn over d=0..1023
//  - fp32 FWHT in reference butterfly order, fp32 scale, then >0
//
// R3: packed FFMA2 (fma.rn.f32x2) — two independent IEEE fp32 FMAs per
// instruction, lanes = adjacent output rows. Chain per element unchanged.
//
// x [32768,1024] fp32, W [128,1024] fp32, out [32768,128] fp32.

#define MOUT 128
#define BM   128
#define BK   16

__device__ __forceinline__ void ffma2(unsigned long long& d,
                                      unsigned long long a,
                                      unsigned long long b) {
    asm("fma.rn.f32x2 %0, %1, %2, %0;" : "+l"(d) : "l"(a), "l"(b));
}

__global__ void __launch_bounds__(256, 2)
gemm_fwht_sign_kernel(const float* __restrict__ x, const float* __restrict__ W,
                      float* __restrict__ out, int K) {
    // smem: GEMM tiles (As 8KB + Bs2 16KB) overlaid with FWHT row buffer (33792B)
    __shared__ __align__(16) char smbuf[64 * (MOUT + 4) * 4];
    float (*As)[BM]        = reinterpret_cast<float(*)[BM]>(smbuf);          // As[k][row]
    float (*Bs2)[2 * MOUT] = reinterpret_cast<float(*)[2 * MOUT]>(smbuf + BK * BM * 4); // dup pairs
    float (*hb)[MOUT + 4]  = reinterpret_cast<float(*)[MOUT + 4]>(smbuf);

    const int tid = threadIdx.x;      // 0..255
    const int tr  = tid >> 4;         // 0..15 (row group: rows tr*8..tr*8+7)
    const int tc  = tid & 15;         // 0..15 (col group: cols tc*8..tc*8+7)
    const int block_row = blockIdx.x * BM;

    const int r0 = tid >> 2;          // 0..63
    const int q0 = tid & 3;

    const float4* xA0 = (const float4*)(x + (size_t)(block_row + r0) * K) + q0;
    const float4* xA1 = (const float4*)(x + (size_t)(block_row + r0 + 64) * K) + q0;
    const float4* wB0 = (const float4*)(W + (size_t)r0 * K) + q0;
    const float4* wB1 = (const float4*)(W + (size_t)(r0 + 64) * K) + q0;

    // acc[i2][j]: packed pair = (row 2*i2, row 2*i2+1) at col j. 0ull == (0.f,0.f)
    unsigned long long acc[4][8];
#pragma unroll
    for (int i = 0; i < 4; ++i)
#pragma unroll
        for (int j = 0; j < 8; ++j) acc[i][j] = 0ull;

    const int nkt = K / BK;           // 64

    float4 pa0 = xA0[0];
    float4 pa1 = xA1[0];
    float4 pb0 = wB0[0];
    float4 pb1 = wB1[0];

    for (int kt = 0; kt < nkt; ++kt) {
        const int kc = q0 * 4;
        // A: k-major, plain
        As[kc + 0][r0] = pa0.x; As[kc + 1][r0] = pa0.y;
        As[kc + 2][r0] = pa0.z; As[kc + 3][r0] = pa0.w;
        As[kc + 0][r0 + 64] = pa1.x; As[kc + 1][r0 + 64] = pa1.y;
        As[kc + 2][r0 + 64] = pa1.z; As[kc + 3][r0 + 64] = pa1.w;
        // B: duplicated pairs (w,w) so FFMA2 broadcast needs no packing
        {
            const float bv[8] = {pb0.x, pb0.y, pb0.z, pb0.w, pb1.x, pb1.y, pb1.z, pb1.w};
#pragma unroll
            for (int i = 0; i < 4; ++i) {
                *(float2*)&Bs2[kc + i][2 * r0]        = make_float2(bv[i], bv[i]);
                *(float2*)&Bs2[kc + i][2 * (r0 + 64)] = make_float2(bv[4 + i], bv[4 + i]);
            }
        }
        __syncthreads();

        if (kt + 1 < nkt) {
            const int off = (kt + 1) * (BK / 4);
            pa0 = xA0[off]; pa1 = xA1[off];
            pb0 = wB0[off]; pb1 = wB1[off];
        }

        // sequential k accumulation; each lane = one independent fp32 fma chain
#pragma unroll
        for (int k = 0; k < BK; ++k) {
            const ulonglong2 aA = *(const ulonglong2*)&As[k][tr * 8];      // rows (0,1),(2,3)
            const ulonglong2 aB = *(const ulonglong2*)&As[k][tr * 8 + 4];  // rows (4,5),(6,7)
            const float* bp = &Bs2[k][tc * 16];
            const ulonglong2 b0 = *(const ulonglong2*)(bp);
            const ulonglong2 b1 = *(const ulonglong2*)(bp + 4);
            const ulonglong2 b2 = *(const ulonglong2*)(bp + 8);
            const ulonglong2 b3 = *(const ulonglong2*)(bp + 12);
            const unsigned long long A[4] = {aA.x, aA.y, aB.x, aB.y};
            const unsigned long long B[8] = {b0.x, b0.y, b1.x, b1.y,
                                             b2.x, b2.y, b3.x, b3.y};
#pragma unroll
            for (int i = 0; i < 4; ++i)
#pragma unroll
                for (int j = 0; j < 8; ++j)
                    ffma2(acc[i][j], A[i], B[j]);
        }
        __syncthreads();
    }

    // ---- epilogue: fp32 FWHT along m (reference butterfly order) + sign ----
    const float scale = 0.08838834764831844f;   // fp32( 1/sqrt(128) )

    for (int hs = 0; hs < 2; ++hs) {            // rows [0,64) then [64,128)
        __syncthreads();
        if ((tr >> 3) == hs) {
            const int rbase = (tr & 7) * 8;
#pragma unroll
            for (int i = 0; i < 4; ++i)
#pragma unroll
                for (int j = 0; j < 8; ++j) {
                    const float2 v = *(const float2*)&acc[i][j];
                    hb[rbase + 2 * i][tc * 8 + j]     = v.x;
                    hb[rbase + 2 * i + 1][tc * 8 + j] = v.y;
                }
        }
        __syncthreads();

        for (int half = 1; half < MOUT; half <<= 1) {
#pragma unroll
            for (int p = 0; p < 16; ++p) {      // 4096 pairs / 256 threads
                const int pidx = tid + p * 256;
                const int row = pidx >> 6;
                const int t   = pidx & 63;
                const int j   = ((t & ~(half - 1)) << 1) | (t & (half - 1));
                const float a = hb[row][j];
                const float b = hb[row][j + half];
                hb[row][j]        = a + b;
                hb[row][j + half] = a - b;
            }
            __syncthreads();
        }

#pragma unroll
        for (int p = 0; p < 8; ++p) {           // 2048 float4 stores
            const int f4  = tid + p * 256;
            const int row = f4 >> 5;
            const int c   = (f4 & 31) * 4;
            float4 v = *(const float4*)&hb[row][c];
            float4 o;
            o.x = (v.x * scale > 0.0f) ? 1.0f : 0.0f;
            o.y = (v.y * scale > 0.0f) ? 1.0f : 0.0f;
            o.z = (v.z * scale > 0.0f) ? 1.0f : 0.0f;
            o.w = (v.w * scale > 0.0f) ? 1.0f : 0.0f;
            *(float4*)(out + (size_t)(block_row + hs * 64 + row) * MOUT + c) = o;
        }
    }
}

extern "C" void kernel_launch(void* const* d_in, const int* in_sizes, int n_in,
                              void* d_out, int out_size) {
    const float* x = (const float*)d_in[0];   // [rows, K]
    const float* W = (const float*)d_in[1];   // [128, K]
    float* out = (float*)d_out;               // [rows, 128]

    const int K = in_sizes[1] / MOUT;         // 1024
    const int rows = in_sizes[0] / K;         // 32768

    gemm_fwht_sign_kernel<<<rows / BM, 256>>>(x, W, out, K);
}

// round 4
// speedup vs baseline: 2.6890x; 2.6890x over previous
#include <cuda_runtime.h>
#include <cuda_bf16.h>

// out[row,m] = ( fp32FWHT_m( sum_d fma-chain x[row,d]*W[m,d] ) * (1/sqrt(128)) > 0 ) ? 1 : 0
//
// Bit-exact vs CPU fp32 reference (rel_err == 0.0 verified in R2/R3):
//  - one fp32 accumulator per output element, strictly sequential fma.rn over d
//  - fp32 FWHT in reference butterfly order, fp32 scale, then >0
//
// R4: FFMA2 (fma.rn.f32x2, lanes = adjacent rows) with R2's exact memory plan:
//  - A row-pairs come free from the k-major As tile (same 2x LDS.128 as R2)
//  - B broadcast pairs built in registers via mov.b64 {b,b} (alu pipe), NO smem dup
//
// x [32768,1024] fp32, W [128,1024] fp32, out [32768,128] fp32.

#define MOUT 128
#define BM   128
#define BK   16

__device__ __forceinline__ void ffma2(unsigned long long& d,
                                      unsigned long long a,
                                      unsigned long long b) {
    asm("fma.rn.f32x2 %0, %1, %2, %0;" : "+l"(d) : "l"(a), "l"(b));
}

__device__ __forceinline__ unsigned long long dup2(float v) {
    unsigned long long r;
    asm("mov.b64 %0, {%1, %1};" : "=l"(r) : "f"(v));
    return r;
}

__global__ void __launch_bounds__(256, 2)
gemm_fwht_sign_kernel(const float* __restrict__ x, const float* __restrict__ W,
                      float* __restrict__ out, int K) {
    // smem: GEMM tiles overlaid with the FWHT row buffer (exactly as in R2)
    __shared__ __align__(16) char smbuf[64 * (MOUT + 4) * 4];   // 33792 B
    float (*As)[BM]       = reinterpret_cast<float(*)[BM]>(smbuf);           // As[k][row]
    float (*Bs)[MOUT]     = reinterpret_cast<float(*)[MOUT]>(smbuf + BK * BM * 4); // Bs[k][m]
    float (*hb)[MOUT + 4] = reinterpret_cast<float(*)[MOUT + 4]>(smbuf);

    const int tid = threadIdx.x;      // 0..255
    const int tr  = tid >> 4;         // 0..15 (rows tr*8 .. tr*8+7)
    const int tc  = tid & 15;         // 0..15 (cols tc*8 .. tc*8+7)
    const int block_row = blockIdx.x * BM;

    const int r0 = tid >> 2;          // 0..63
    const int q0 = tid & 3;

    const float4* xA0 = (const float4*)(x + (size_t)(block_row + r0) * K) + q0;
    const float4* xA1 = (const float4*)(x + (size_t)(block_row + r0 + 64) * K) + q0;
    const float4* wB0 = (const float4*)(W + (size_t)r0 * K) + q0;
    const float4* wB1 = (const float4*)(W + (size_t)(r0 + 64) * K) + q0;

    // acc[i][j]: packed pair = (row tr*8+2i, row tr*8+2i+1) at col tc*8+j
    unsigned long long acc[4][8];
#pragma unroll
    for (int i = 0; i < 4; ++i)
#pragma unroll
        for (int j = 0; j < 8; ++j) acc[i][j] = 0ull;   // (0.f, 0.f)

    const int nkt = K / BK;           // 64

    float4 pa0 = xA0[0];
    float4 pa1 = xA1[0];
    float4 pb0 = wB0[0];
    float4 pb1 = wB1[0];

    for (int kt = 0; kt < nkt; ++kt) {
        const int kc = q0 * 4;
        As[kc + 0][r0] = pa0.x; As[kc + 1][r0] = pa0.y;
        As[kc + 2][r0] = pa0.z; As[kc + 3][r0] = pa0.w;
        As[kc + 0][r0 + 64] = pa1.x; As[kc + 1][r0 + 64] = pa1.y;
        As[kc + 2][r0 + 64] = pa1.z; As[kc + 3][r0 + 64] = pa1.w;
        Bs[kc + 0][r0] = pb0.x; Bs[kc + 1][r0] = pb0.y;
        Bs[kc + 2][r0] = pb0.z; Bs[kc + 3][r0] = pb0.w;
        Bs[kc + 0][r0 + 64] = pb1.x; Bs[kc + 1][r0 + 64] = pb1.y;
        Bs[kc + 2][r0 + 64] = pb1.z; Bs[kc + 3][r0 + 64] = pb1.w;
        __syncthreads();

        if (kt + 1 < nkt) {
            const int off = (kt + 1) * (BK / 4);
            pa0 = xA0[off]; pa1 = xA1[off];
            pb0 = wB0[off]; pb1 = wB1[off];
        }

        // sequential k accumulation; each fp32 lane = one independent fma chain
#pragma unroll
        for (int k = 0; k < BK; ++k) {
            // A: natural row pairs, straight from the same LDS.128s R2 used
            const ulonglong2 aA = *(const ulonglong2*)&As[k][tr * 8];      // (2i=0),(2i=1)
            const ulonglong2 aB = *(const ulonglong2*)&As[k][tr * 8 + 4];  // (2i=2),(2i=3)
            const unsigned long long A[4] = {aA.x, aA.y, aB.x, aB.y};
            // B: scalar loads (same bytes as R2), dup-pairs built in registers
            const float4 b0 = *(const float4*)&Bs[k][tc * 8];
            const float4 b1 = *(const float4*)&Bs[k][tc * 8 + 4];
            const unsigned long long B[8] = {
                dup2(b0.x), dup2(b0.y), dup2(b0.z), dup2(b0.w),
                dup2(b1.x), dup2(b1.y), dup2(b1.z), dup2(b1.w)};
#pragma unroll
            for (int i = 0; i < 4; ++i)
#pragma unroll
                for (int j = 0; j < 8; ++j)
                    ffma2(acc[i][j], A[i], B[j]);
        }
        __syncthreads();
    }

    // ---- epilogue: fp32 FWHT along m (reference butterfly order) + sign ----
    const float scale = 0.08838834764831844f;   // fp32( 1/sqrt(128) )

    for (int hs = 0; hs < 2; ++hs) {            // rows [0,64) then [64,128)
        __syncthreads();
        if ((tr >> 3) == hs) {
            const int rbase = (tr & 7) * 8;
#pragma unroll
            for (int i = 0; i < 4; ++i)
#pragma unroll
                for (int j = 0; j < 8; ++j) {
                    const float2 v = *(const float2*)&acc[i][j];
                    hb[rbase + 2 * i][tc * 8 + j]     = v.x;
                    hb[rbase + 2 * i + 1][tc * 8 + j] = v.y;
                }
        }
        __syncthreads();

        for (int half = 1; half < MOUT; half <<= 1) {
#pragma unroll
            for (int p = 0; p < 16; ++p) {      // 4096 pairs / 256 threads
                const int pidx = tid + p * 256;
                const int row = pidx >> 6;
                const int t   = pidx & 63;
                const int j   = ((t & ~(half - 1)) << 1) | (t & (half - 1));
                const float a = hb[row][j];
                const float b = hb[row][j + half];
                hb[row][j]        = a + b;
                hb[row][j + half] = a - b;
            }
            __syncthreads();
        }

#pragma unroll
        for (int p = 0; p < 8; ++p) {           // 2048 float4 stores
            const int f4  = tid + p * 256;
            const int row = f4 >> 5;
            const int c   = (f4 & 31) * 4;
            float4 v = *(const float4*)&hb[row][c];
            float4 o;
            o.x = (v.x * scale > 0.0f) ? 1.0f : 0.0f;
            o.y = (v.y * scale > 0.0f) ? 1.0f : 0.0f;
            o.z = (v.z * scale > 0.0f) ? 1.0f : 0.0f;
            o.w = (v.w * scale > 0.0f) ? 1.0f : 0.0f;
            *(float4*)(out + (size_t)(block_row + hs * 64 + row) * MOUT + c) = o;
        }
    }
}

extern "C" void kernel_launch(void* const* d_in, const int* in_sizes, int n_in,
                              void* d_out, int out_size) {
    const float* x = (const float*)d_in[0];   // [rows, K]
    const float* W = (const float*)d_in[1];   // [128, K]
    float* out = (float*)d_out;               // [rows, 128]

    const int K = in_sizes[1] / MOUT;         // 1024
    const int rows = in_sizes[0] / K;         // 32768

    gemm_fwht_sign_kernel<<<rows / BM, 256>>>(x, W, out, K);
}